// round 15
// baseline (speedup 1.0000x reference)
#include <cuda_runtime.h>
#include <cuda_bf16.h>
#include <math.h>
#include <math_constants.h>
#include <stdint.h>

#define DIM    256
#define NEMB   2048
#define NROWS  65536
#define QELEMS (NROWS * DIM)
#define NPART  8192               // recheck_gather blocks
#define CAP    64
#define MARGIN 3.0f

#define M_CTA  128
#define CHUNK  32
#define NCHUNK (NEMB / CHUNK)     // 64

// ---------------- device scratch (no allocations allowed) ----------------
__device__ float         g_embedT[NEMB * DIM];    // fp32 [j][k]
__device__ float4        g_sumE2p[NEMB];          // 4 d-range partials of ||e_j||^2
__device__ __nv_bfloat16 g_embB[NEMB * DIM];      // bf16 [j][k]
__device__ int           g_counts[NEMB];
__device__ int           g_candCnt[NROWS];
__device__ int           g_cand[NROWS * CAP];
__device__ double        g_partials[NPART];
__device__ unsigned int  g_done;

// ---------------- helpers ----------------
__device__ __forceinline__ uint32_t smem_to_u32(const void* p) {
    uint32_t a;
    asm("{ .reg .u64 t; cvta.to.shared.u64 t, %1; cvt.u32.u64 %0, t; }"
        : "=r"(a) : "l"(p));
    return a;
}
__device__ __forceinline__ uint32_t fenc(float f) {
    uint32_t u = __float_as_uint(f);
    return u ^ ((u >> 31) ? 0xFFFFFFFFu : 0x80000000u);
}
__device__ __forceinline__ float fdec(uint32_t u) {
    return __uint_as_float(u ^ ((u & 0x80000000u) ? 0x80000000u : 0xFFFFFFFFu));
}
__device__ __forceinline__ float se2_combine(float4 p) {
    return __fadd_rn(__fadd_rn(p.x, p.y), __fadd_rn(p.z, p.w));
}

__device__ __forceinline__ void ldsm_x4(uint32_t (&r)[4], uint32_t addr) {
    asm volatile("ldmatrix.sync.aligned.m8n8.x4.shared.b16 {%0,%1,%2,%3}, [%4];"
        : "=r"(r[0]), "=r"(r[1]), "=r"(r[2]), "=r"(r[3]) : "r"(addr));
}

__device__ __forceinline__ void mma_bf16(float (&c)[4], const uint32_t (&a)[4],
                                         uint32_t b0, uint32_t b1) {
    asm volatile(
        "mma.sync.aligned.m16n8k16.row.col.f32.bf16.bf16.f32 "
        "{%0,%1,%2,%3}, {%4,%5,%6,%7}, {%8,%9}, {%0,%1,%2,%3};"
        : "+f"(c[0]), "+f"(c[1]), "+f"(c[2]), "+f"(c[3])
        : "r"(a[0]), "r"(a[1]), "r"(a[2]), "r"(a[3]), "r"(b0), "r"(b1));
}

#define CP_ASYNC16(dst, src) \
    asm volatile("cp.async.cg.shared.global [%0], [%1], 16;" \
        :: "r"(dst), "l"(src) : "memory")
#define CP_COMMIT()  asm volatile("cp.async.commit_group;" ::: "memory")
#define CP_WAIT1()   asm volatile("cp.async.wait_group 1;" ::: "memory")
#define CP_WAIT0()   asm volatile("cp.async.wait_group 0;" ::: "memory")

// ============================================================
// Kernel 0: transpose + bf16 convert + partial ||e||^2.
// 256 blocks = 64 j-groups x 4 d-groups.
// ============================================================
__global__ void __launch_bounds__(256) prep_kernel(const float* __restrict__ embed) {
    __shared__ float psum[8][32];
    const int jg  = blockIdx.x & 63;
    const int dg  = blockIdx.x >> 6;
    const int jl  = threadIdx.x & 31;
    const int seg = threadIdx.x >> 5;
    const int j   = jg * 32 + jl;
    const int d0  = dg * 64 + seg * 8;

    float s = 0.0f;
    #pragma unroll
    for (int dd = 0; dd < 8; dd++) {
        int d = d0 + dd;
        float v = embed[(size_t)d * NEMB + j];
        g_embedT[(size_t)j * DIM + d] = v;
        g_embB[(size_t)j * DIM + d]   = __float2bfloat16_rn(v);
        s = __fadd_rn(s, __fmul_rn(v, v));
    }
    psum[seg][jl] = s;
    __syncthreads();
    if (seg == 0) {
        float t = 0.0f;
        #pragma unroll
        for (int q = 0; q < 8; q++) t = __fadd_rn(t, psum[q][jl]);
        ((float*)&g_sumE2p[j])[dg] = t;
        if (dg == 0) g_counts[j] = 0;
    }
    if (blockIdx.x == 0 && threadIdx.x == 0) g_done = 0u;
}

// ============================================================
// Kernel 1: bf16 mma.sync distance, DOUBLE-BUFFERED B.
// 128 rows/CTA, 256 thr, 2 CTAs/SM. 64 chunks of 32 codes.
// 8 warps = 4M x 2N, warp tile 32 rows x 16 codes.
// Publish row-best -> sync -> margin test (proven semantics).
// ============================================================
#define APITCH 528
#define A_OFF  0
#define B0_OFF (M_CTA * APITCH)                  // 67584
#define B1_OFF (B0_OFF + CHUNK * APITCH)         // 84480
#define RB_OFF (B1_OFF + CHUNK * APITCH)         // 101376
#define SE_OFF (RB_OFF + M_CTA * 4)              // 101888
#define SMEM_DIST (SE_OFF + CHUNK * 4)           // 102016

__global__ void __launch_bounds__(256, 2) dist_kernel(const float* __restrict__ input) {
    extern __shared__ __align__(16) char smraw[];
    const uint32_t sbase = smem_to_u32(smraw);
    const uint32_t asU   = sbase + A_OFF;
    unsigned int* sRowBest = (unsigned int*)(smraw + RB_OFF);
    float* se2c = (float*)(smraw + SE_OFF);

    const int tid  = threadIdx.x;
    const int wid  = tid >> 5;
    const int lane = tid & 31;
    const int warp_m = wid >> 1;     // 0..3 : 32-row strip
    const int warp_n = wid & 1;      // 0..1 : 16-code group
    const int row0 = blockIdx.x * M_CTA;

    if (tid < M_CTA) {
        g_candCnt[row0 + tid] = 0;
        sRowBest[tid] = 0xFFFFFFFFu;
    }

    // ---- prologue: stage B chunk 0 into buf0 (1024 vec16, 4/thread) ----
    #pragma unroll
    for (int it = 0; it < 4; it++) {
        int idx = tid + it * 256;
        int n = idx >> 5, v = idx & 31;
        const void* src = (const void*)(g_embB + (size_t)n * DIM + v * 8);
        CP_ASYNC16(sbase + B0_OFF + n * APITCH + v * 16, src);
    }
    CP_COMMIT();

    // ---- load + convert A: 128 rows x 256 fp32 -> bf16 SMEM ----
    {
        const float4* in4 = (const float4*)(input + (size_t)row0 * DIM);
        #pragma unroll
        for (int it = 0; it < 32; it++) {
            int idx = tid + it * 256;
            int r = idx >> 6, v = idx & 63;
            float4 f = in4[idx];
            __nv_bfloat162 p0 = __floats2bfloat162_rn(f.x, f.y);
            __nv_bfloat162 p1 = __floats2bfloat162_rn(f.z, f.w);
            uint2 st;
            st.x = *reinterpret_cast<unsigned int*>(&p0);
            st.y = *reinterpret_cast<unsigned int*>(&p1);
            *(uint2*)(smraw + A_OFF + r * APITCH + v * 8) = st;
        }
    }

    // rows owned by this thread in the epilogue
    int lrow[2][2];
    #pragma unroll
    for (int mi = 0; mi < 2; mi++)
        #pragma unroll
        for (int h = 0; h < 2; h++)
            lrow[mi][h] = warp_m * 32 + mi * 16 + (lane >> 2) + h * 8;

    const uint32_t a_base = asU + (warp_m * 32 + (lane & 15)) * APITCH
                          + ((lane >> 4) & 1) * 16;
    // B fragment: 16 codes per warp, one ldsm_x4 per ks
    const uint32_t b_off = (warp_n * 16 + (lane & 7) + ((lane & 16) >> 1)) * APITCH
                         + ((lane >> 3) & 1) * 16;

    #pragma unroll 1
    for (int c = 0; c < NCHUNK; c++) {
        const int j0 = c * CHUNK;

        // stage chunk c+1 into the other buffer; chunk c already landed
        if (c + 1 < NCHUNK) {
            const uint32_t bU = sbase + (((c + 1) & 1) ? B1_OFF : B0_OFF);
            #pragma unroll
            for (int it = 0; it < 4; it++) {
                int idx = tid + it * 256;
                int n = idx >> 5, v = idx & 31;
                const void* src = (const void*)(g_embB + (size_t)(j0 + CHUNK + n) * DIM + v * 8);
                CP_ASYNC16(bU + n * APITCH + v * 16, src);
            }
            CP_COMMIT();
            CP_WAIT1();          // chunk c's group complete (0 exposed latency)
        } else {
            CP_WAIT0();
        }
        if (tid < CHUNK)
            se2c[tid] = se2_combine(__ldg(&g_sumE2p[j0 + tid]));
        __syncthreads();         // publish buf c + se2c

        const uint32_t bbase = sbase + ((c & 1) ? B1_OFF : B0_OFF) + b_off;

        float acc[2][2][4];
        #pragma unroll
        for (int mi = 0; mi < 2; mi++)
            #pragma unroll
            for (int ni = 0; ni < 2; ni++)
                #pragma unroll
                for (int q = 0; q < 4; q++) acc[mi][ni][q] = 0.0f;

        #pragma unroll 4
        for (int ks = 0; ks < 16; ks++) {
            uint32_t af[2][4], bf[4];
            ldsm_x4(af[0], a_base + ks * 32);
            ldsm_x4(af[1], a_base + 16 * APITCH + ks * 32);
            ldsm_x4(bf, bbase + ks * 32);
            #pragma unroll
            for (int mi = 0; mi < 2; mi++) {
                mma_bf16(acc[mi][0], af[mi], bf[0], bf[1]);
                mma_bf16(acc[mi][1], af[mi], bf[2], bf[3]);
            }
        }

        // ---- keys d = se2 - 2*dot; per-(mi,h) minima ----
        float lmin[2][2] = {{CUDART_INF_F, CUDART_INF_F},
                            {CUDART_INF_F, CUDART_INF_F}};
        #pragma unroll
        for (int ni = 0; ni < 2; ni++) {
            int li = warp_n * 16 + ni * 8 + ((lane & 3) << 1);
            float se0 = se2c[li];
            float se1 = se2c[li + 1];
            #pragma unroll
            for (int mi = 0; mi < 2; mi++) {
                #pragma unroll
                for (int q = 0; q < 4; q++) {
                    float d = fmaf(acc[mi][ni][q], -2.0f, (q & 1) ? se1 : se0);
                    acc[mi][ni][q] = d;
                    lmin[mi][q >> 1] = fminf(lmin[mi][q >> 1], d);
                }
            }
        }
        // publish chunk minima (conditional atomic), then sync
        #pragma unroll
        for (int mi = 0; mi < 2; mi++)
            #pragma unroll
            for (int h = 0; h < 2; h++) {
                int r = lrow[mi][h];
                if (fenc(lmin[mi][h]) < sRowBest[r])
                    atomicMin(&sRowBest[r], fenc(lmin[mi][h]));
            }
        __syncthreads();         // row-best stable + all B reads of buf c done

        // margin test vs row-global running best, append candidates
        #pragma unroll
        for (int mi = 0; mi < 2; mi++) {
            #pragma unroll
            for (int h = 0; h < 2; h++) {
                float rb = fdec(sRowBest[lrow[mi][h]]) + MARGIN;
                int g = row0 + lrow[mi][h];
                #pragma unroll
                for (int ni = 0; ni < 2; ni++) {
                    #pragma unroll
                    for (int qq = 0; qq < 2; qq++) {
                        float d = acc[mi][ni][h * 2 + qq];
                        if (d < rb) {
                            int pos = atomicAdd(&g_candCnt[g], 1);
                            if (pos < CAP)
                                g_cand[(size_t)g * CAP + pos] =
                                    j0 + warp_n * 16 + ni * 8 + ((lane & 3) << 1) + qq;
                        }
                    }
                }
            }
        }
    }
}

// ============================================================
// Kernel 2: exact re-check + gather + STE + diff + hist,
// with LAST-BLOCK finalize. Warp per row (round-13 proven).
// ============================================================
__global__ void __launch_bounds__(256) recheck_gather_kernel(
    const float* __restrict__ input, float* __restrict__ outQ,
    float* __restrict__ indOutF,
    float* __restrict__ outDiff, float* __restrict__ outPerp)
{
    __shared__ float xs[8][256];
    __shared__ double wsum[8];
    __shared__ double sred[256];
    __shared__ int sLast;
    const int w = threadIdx.x >> 5, l = threadIdx.x & 31;
    const int row = blockIdx.x * 8 + w;

    const float4* xr4 = (const float4*)(input + (size_t)row * DIM);
    float4 xa = xr4[l];
    float4 xb = xr4[l + 32];
    *(float4*)&xs[w][l * 4]       = xa;
    *(float4*)&xs[w][128 + l * 4] = xb;
    __syncwarp();

    float xr[8];
    #pragma unroll
    for (int u = 0; u < 8; u++) xr[u] = xs[w][l * 8 + u];

    float p2 = 0.0f;
    #pragma unroll
    for (int u = 0; u < 8; u++) p2 = fmaf(xr[u], xr[u], p2);
    #pragma unroll
    for (int o = 16; o > 0; o >>= 1) p2 += __shfl_xor_sync(0xffffffffu, p2, o);
    const float sx2 = p2;

    const int cnt = g_candCnt[row];
    float bd = CUDART_INF_F; int bi = 0x7fffffff;

    const int limit = (cnt <= CAP) ? cnt : NEMB;
    for (int c = 0; c < limit; c++) {
        int j = (cnt <= CAP) ? g_cand[(size_t)row * CAP + c] : c;
        const float4* e4 = (const float4*)(g_embedT + (size_t)j * DIM);
        float4 e0 = e4[l * 2], e1 = e4[l * 2 + 1];
        float p = 0.0f;
        p = fmaf(xr[0], e0.x, p); p = fmaf(xr[1], e0.y, p);
        p = fmaf(xr[2], e0.z, p); p = fmaf(xr[3], e0.w, p);
        p = fmaf(xr[4], e1.x, p); p = fmaf(xr[5], e1.y, p);
        p = fmaf(xr[6], e1.z, p); p = fmaf(xr[7], e1.w, p);
        #pragma unroll
        for (int o = 16; o > 0; o >>= 1) p += __shfl_xor_sync(0xffffffffu, p, o);
        float se2 = se2_combine(__ldg(&g_sumE2p[j]));
        float d = __fadd_rn(__fsub_rn(sx2, __fmul_rn(2.0f, p)), se2);
        if (d < bd || (d == bd && j < bi)) { bd = d; bi = j; }
    }

    if (l == 0) {
        indOutF[row] = (float)bi;
        atomicAdd(&g_counts[bi], 1);
    }

    // ---- gather + straight-through + diff partial ----
    const float4* erow = (const float4*)(g_embedT + (size_t)bi * DIM);
    float4* qrow = (float4*)(outQ + (size_t)row * DIM);
    float4 e0 = __ldg(&erow[l * 2]);
    float4 e1 = __ldg(&erow[l * 2 + 1]);

    float dx[8];
    dx[0] = __fsub_rn(e0.x, xr[0]); dx[1] = __fsub_rn(e0.y, xr[1]);
    dx[2] = __fsub_rn(e0.z, xr[2]); dx[3] = __fsub_rn(e0.w, xr[3]);
    dx[4] = __fsub_rn(e1.x, xr[4]); dx[5] = __fsub_rn(e1.y, xr[5]);
    dx[6] = __fsub_rn(e1.z, xr[6]); dx[7] = __fsub_rn(e1.w, xr[7]);

    float4 q0, q1;
    q0.x = __fadd_rn(xr[0], dx[0]); q0.y = __fadd_rn(xr[1], dx[1]);
    q0.z = __fadd_rn(xr[2], dx[2]); q0.w = __fadd_rn(xr[3], dx[3]);
    q1.x = __fadd_rn(xr[4], dx[4]); q1.y = __fadd_rn(xr[5], dx[5]);
    q1.z = __fadd_rn(xr[6], dx[6]); q1.w = __fadd_rn(xr[7], dx[7]);
    qrow[l * 2]     = q0;
    qrow[l * 2 + 1] = q1;

    double s = 0.0;
    #pragma unroll
    for (int u = 0; u < 8; u++)
        s += (double)__fmul_rn(dx[u], dx[u]);
    #pragma unroll
    for (int o = 16; o > 0; o >>= 1) s += __shfl_xor_sync(0xffffffffu, s, o);
    if (l == 0) wsum[w] = s;
    __syncthreads();
    if (threadIdx.x == 0) {
        double acc = 0.0;
        #pragma unroll
        for (int i = 0; i < 8; i++) acc += wsum[i];
        g_partials[blockIdx.x] = acc;
        __threadfence();
        unsigned int old = atomicAdd(&g_done, 1u);
        sLast = (old == NPART - 1u) ? 1 : 0;
    }
    __syncthreads();

    // ---- LAST block: deterministic finalize (diff + perplexity) ----
    if (sLast) {
        const int tid = threadIdx.x;
        double acc = 0.0;
        for (int i = tid; i < NPART; i += 256) acc += g_partials[i];
        sred[tid] = acc;
        __syncthreads();
        for (int o = 128; o > 0; o >>= 1) {
            if (tid < o) sred[tid] += sred[tid + o];
            __syncthreads();
        }
        if (tid == 0) *outDiff = (float)(sred[0] / (double)QELEMS);
        __syncthreads();

        double ps = 0.0;
        for (int j = tid; j < NEMB; j += 256) {
            float p  = (float)g_counts[j] * (1.0f / 65536.0f);
            float cl = fmaxf(p, 1e-7f);
            ps += (double)__fmul_rn(p, logf(cl));
        }
        sred[tid] = ps;
        __syncthreads();
        for (int o = 128; o > 0; o >>= 1) {
            if (tid < o) sred[tid] += sred[tid + o];
            __syncthreads();
        }
        if (tid == 0) *outPerp = expf((float)(-sred[0]));
    }
}

// ============================================================
// Output layout (float32): [quantize_st | diff | embed_ind | perplexity]
// ============================================================
extern "C" void kernel_launch(void* const* d_in, const int* in_sizes, int n_in,
                              void* d_out, int out_size) {
    const float* input = (const float*)d_in[0];
    const float* embed = (const float*)d_in[1];
    float* out     = (float*)d_out;
    float* outQ    = out;
    float* outDiff = out + QELEMS;
    float* outInd  = out + QELEMS + 1;
    float* outPerp = out + QELEMS + 1 + NROWS;

    cudaFuncSetAttribute(dist_kernel,
                         cudaFuncAttributeMaxDynamicSharedMemorySize, SMEM_DIST);

    prep_kernel<<<256, 256>>>(embed);
    dist_kernel<<<NROWS / M_CTA, 256, SMEM_DIST>>>(input);
    recheck_gather_kernel<<<NPART, 256>>>(input, outQ, outInd, outDiff, outPerp);
}

// round 16
// speedup vs baseline: 1.2007x; 1.2007x over previous
#include <cuda_runtime.h>
#include <cuda_bf16.h>
#include <math.h>
#include <math_constants.h>
#include <stdint.h>

#define DIM    256
#define NEMB   2048
#define NROWS  65536
#define QELEMS (NROWS * DIM)
#define NPART  8192               // recheck_gather blocks
#define CAP    64
#define MARGIN 3.0f

#define M_CTA  128
#define CHUNK  64
#define NCHUNK (NEMB / CHUNK)     // 32

// ---------------- device scratch (no allocations allowed) ----------------
__device__ float         g_embedT[NEMB * DIM];    // fp32 [j][k]
__device__ float4        g_sumE2p[NEMB];          // 4 d-range partials of ||e_j||^2
__device__ __nv_bfloat16 g_embB[NEMB * DIM];      // bf16 [j][k]
__device__ int           g_counts[NEMB];
__device__ int           g_candCnt[NROWS];
__device__ int           g_cand[NROWS * CAP];
__device__ double        g_partials[NPART];
__device__ unsigned int  g_done;

// ---------------- helpers ----------------
__device__ __forceinline__ uint32_t smem_to_u32(const void* p) {
    uint32_t a;
    asm("{ .reg .u64 t; cvta.to.shared.u64 t, %1; cvt.u32.u64 %0, t; }"
        : "=r"(a) : "l"(p));
    return a;
}
__device__ __forceinline__ uint32_t fenc(float f) {
    uint32_t u = __float_as_uint(f);
    return u ^ ((u >> 31) ? 0xFFFFFFFFu : 0x80000000u);
}
__device__ __forceinline__ float fdec(uint32_t u) {
    return __uint_as_float(u ^ ((u & 0x80000000u) ? 0x80000000u : 0xFFFFFFFFu));
}
__device__ __forceinline__ float se2_combine(float4 p) {
    return __fadd_rn(__fadd_rn(p.x, p.y), __fadd_rn(p.z, p.w));
}

__device__ __forceinline__ void ldsm_x4(uint32_t (&r)[4], uint32_t addr) {
    asm volatile("ldmatrix.sync.aligned.m8n8.x4.shared.b16 {%0,%1,%2,%3}, [%4];"
        : "=r"(r[0]), "=r"(r[1]), "=r"(r[2]), "=r"(r[3]) : "r"(addr));
}

__device__ __forceinline__ void mma_bf16(float (&c)[4], const uint32_t (&a)[4],
                                         uint32_t b0, uint32_t b1) {
    asm volatile(
        "mma.sync.aligned.m16n8k16.row.col.f32.bf16.bf16.f32 "
        "{%0,%1,%2,%3}, {%4,%5,%6,%7}, {%8,%9}, {%0,%1,%2,%3};"
        : "+f"(c[0]), "+f"(c[1]), "+f"(c[2]), "+f"(c[3])
        : "r"(a[0]), "r"(a[1]), "r"(a[2]), "r"(a[3]), "r"(b0), "r"(b1));
}

#define CP_ASYNC16(dst, src) \
    asm volatile("cp.async.cg.shared.global [%0], [%1], 16;" \
        :: "r"(dst), "l"(src) : "memory")
#define CP_COMMIT()  asm volatile("cp.async.commit_group;" ::: "memory")
#define CP_WAIT0()   asm volatile("cp.async.wait_group 0;" ::: "memory")

// ============================================================
// Kernel 0: transpose + bf16 convert + partial ||e||^2.
// 256 blocks = 64 j-groups x 4 d-groups.
// ============================================================
__global__ void __launch_bounds__(256) prep_kernel(const float* __restrict__ embed) {
    __shared__ float psum[8][32];
    const int jg  = blockIdx.x & 63;
    const int dg  = blockIdx.x >> 6;
    const int jl  = threadIdx.x & 31;
    const int seg = threadIdx.x >> 5;
    const int j   = jg * 32 + jl;
    const int d0  = dg * 64 + seg * 8;

    float s = 0.0f;
    #pragma unroll
    for (int dd = 0; dd < 8; dd++) {
        int d = d0 + dd;
        float v = embed[(size_t)d * NEMB + j];
        g_embedT[(size_t)j * DIM + d] = v;
        g_embB[(size_t)j * DIM + d]   = __float2bfloat16_rn(v);
        s = __fadd_rn(s, __fmul_rn(v, v));
    }
    psum[seg][jl] = s;
    __syncthreads();
    if (seg == 0) {
        float t = 0.0f;
        #pragma unroll
        for (int q = 0; q < 8; q++) t = __fadd_rn(t, psum[q][jl]);
        ((float*)&g_sumE2p[j])[dg] = t;
        if (dg == 0) g_counts[j] = 0;
    }
    if (blockIdx.x == 0 && threadIdx.x == 0) g_done = 0u;
}

// ============================================================
// Kernel 1: bf16 mma.sync distance (round-13 proven config).
// 128 rows/CTA, 256 thr, 2 CTAs/SM, CHUNK=64 single-buffered.
// ============================================================
#define APITCH 528
#define A_OFF  0
#define B_OFF  (M_CTA * APITCH)
#define RB_OFF (B_OFF + CHUNK * APITCH)
#define SE_OFF (RB_OFF + M_CTA * 4)
#define SMEM_DIST (SE_OFF + CHUNK * 4)

__global__ void __launch_bounds__(256, 2) dist_kernel(const float* __restrict__ input) {
    extern __shared__ __align__(16) char smraw[];
    const uint32_t sbase = smem_to_u32(smraw);
    const uint32_t asU   = sbase + A_OFF;
    unsigned int* sRowBest = (unsigned int*)(smraw + RB_OFF);
    float* se2c = (float*)(smraw + SE_OFF);

    const int tid  = threadIdx.x;
    const int wid  = tid >> 5;
    const int lane = tid & 31;
    const int warp_m = wid >> 1;
    const int warp_n = wid & 1;
    const int row0 = blockIdx.x * M_CTA;

    if (tid < M_CTA) {
        g_candCnt[row0 + tid] = 0;
        sRowBest[tid] = 0xFFFFFFFFu;
    }

    {
        const float4* in4 = (const float4*)(input + (size_t)row0 * DIM);
        #pragma unroll
        for (int it = 0; it < 32; it++) {
            int idx = tid + it * 256;
            int r = idx >> 6, v = idx & 63;
            float4 f = in4[idx];
            __nv_bfloat162 p0 = __floats2bfloat162_rn(f.x, f.y);
            __nv_bfloat162 p1 = __floats2bfloat162_rn(f.z, f.w);
            uint2 st;
            st.x = *reinterpret_cast<unsigned int*>(&p0);
            st.y = *reinterpret_cast<unsigned int*>(&p1);
            *(uint2*)(smraw + A_OFF + r * APITCH + v * 8) = st;
        }
    }

    int lrow[2][2];
    #pragma unroll
    for (int mi = 0; mi < 2; mi++)
        #pragma unroll
        for (int h = 0; h < 2; h++)
            lrow[mi][h] = warp_m * 32 + mi * 16 + (lane >> 2) + h * 8;

    const uint32_t a_base = asU + (warp_m * 32 + (lane & 15)) * APITCH
                          + ((lane >> 4) & 1) * 16;
    const uint32_t bbase  = sbase + B_OFF
                          + (warp_n * 32 + (lane & 7) + ((lane & 16) >> 1)) * APITCH
                          + ((lane >> 3) & 1) * 16;

    #pragma unroll 1
    for (int c = 0; c < NCHUNK; c++) {
        const int j0 = c * CHUNK;

        __syncthreads();
        #pragma unroll
        for (int it = 0; it < 8; it++) {
            int idx = tid + it * 256;
            int n = idx >> 5, v = idx & 31;
            const void* src = (const void*)(g_embB + (size_t)(j0 + n) * DIM + v * 8);
            CP_ASYNC16(sbase + B_OFF + n * APITCH + v * 16, src);
        }
        CP_COMMIT();
        if (tid < CHUNK)
            se2c[tid] = se2_combine(__ldg(&g_sumE2p[j0 + tid]));
        CP_WAIT0();
        __syncthreads();

        float acc[2][4][4];
        #pragma unroll
        for (int mi = 0; mi < 2; mi++)
            #pragma unroll
            for (int ni = 0; ni < 4; ni++)
                #pragma unroll
                for (int q = 0; q < 4; q++) acc[mi][ni][q] = 0.0f;

        #pragma unroll 4
        for (int ks = 0; ks < 16; ks++) {
            uint32_t af[2][4], bf[2][4];
            ldsm_x4(af[0], a_base + ks * 32);
            ldsm_x4(af[1], a_base + 16 * APITCH + ks * 32);
            ldsm_x4(bf[0], bbase + ks * 32);
            ldsm_x4(bf[1], bbase + 16 * APITCH + ks * 32);
            #pragma unroll
            for (int mi = 0; mi < 2; mi++) {
                mma_bf16(acc[mi][0], af[mi], bf[0][0], bf[0][1]);
                mma_bf16(acc[mi][1], af[mi], bf[0][2], bf[0][3]);
                mma_bf16(acc[mi][2], af[mi], bf[1][0], bf[1][1]);
                mma_bf16(acc[mi][3], af[mi], bf[1][2], bf[1][3]);
            }
        }

        float lmin[2][2] = {{CUDART_INF_F, CUDART_INF_F},
                            {CUDART_INF_F, CUDART_INF_F}};
        #pragma unroll
        for (int ni = 0; ni < 4; ni++) {
            int li = warp_n * 32 + ni * 8 + ((lane & 3) << 1);
            float se0 = se2c[li];
            float se1 = se2c[li + 1];
            #pragma unroll
            for (int mi = 0; mi < 2; mi++) {
                #pragma unroll
                for (int q = 0; q < 4; q++) {
                    float d = fmaf(acc[mi][ni][q], -2.0f, (q & 1) ? se1 : se0);
                    acc[mi][ni][q] = d;
                    lmin[mi][q >> 1] = fminf(lmin[mi][q >> 1], d);
                }
            }
        }
        #pragma unroll
        for (int mi = 0; mi < 2; mi++)
            #pragma unroll
            for (int h = 0; h < 2; h++) {
                int r = lrow[mi][h];
                if (fenc(lmin[mi][h]) < sRowBest[r])
                    atomicMin(&sRowBest[r], fenc(lmin[mi][h]));
            }
        __syncthreads();

        #pragma unroll
        for (int mi = 0; mi < 2; mi++) {
            #pragma unroll
            for (int h = 0; h < 2; h++) {
                float rb = fdec(sRowBest[lrow[mi][h]]) + MARGIN;
                int g = row0 + lrow[mi][h];
                #pragma unroll
                for (int ni = 0; ni < 4; ni++) {
                    #pragma unroll
                    for (int qq = 0; qq < 2; qq++) {
                        float d = acc[mi][ni][h * 2 + qq];
                        if (d < rb) {
                            int pos = atomicAdd(&g_candCnt[g], 1);
                            if (pos < CAP)
                                g_cand[(size_t)g * CAP + pos] =
                                    j0 + warp_n * 32 + ni * 8 + ((lane & 3) << 1) + qq;
                        }
                    }
                }
            }
        }
    }
}

// ============================================================
// Kernel 2: exact re-check + gather + STE + diff + hist.
// FAST PATH: candCnt==1 -> index decided, no distance compute.
// Warp per row; last block finalizes diff + perplexity.
// ============================================================
__global__ void __launch_bounds__(256) recheck_gather_kernel(
    const float* __restrict__ input, float* __restrict__ outQ,
    float* __restrict__ indOutF,
    float* __restrict__ outDiff, float* __restrict__ outPerp)
{
    __shared__ float xs[8][256];
    __shared__ double wsum[8];
    __shared__ double sred[256];
    __shared__ int sLast;
    const int w = threadIdx.x >> 5, l = threadIdx.x & 31;
    const int row = blockIdx.x * 8 + w;

    const float4* xr4 = (const float4*)(input + (size_t)row * DIM);
    float4 xa = xr4[l];
    float4 xb = xr4[l + 32];
    *(float4*)&xs[w][l * 4]       = xa;
    *(float4*)&xs[w][128 + l * 4] = xb;
    __syncwarp();

    float xr[8];
    #pragma unroll
    for (int u = 0; u < 8; u++) xr[u] = xs[w][l * 8 + u];

    const int cnt = g_candCnt[row];
    int bi;

    if (cnt == 1) {
        // candidate-set invariant: the single candidate IS the argmin
        bi = g_cand[(size_t)row * CAP];
    } else {
        float p2 = 0.0f;
        #pragma unroll
        for (int u = 0; u < 8; u++) p2 = fmaf(xr[u], xr[u], p2);
        #pragma unroll
        for (int o = 16; o > 0; o >>= 1) p2 += __shfl_xor_sync(0xffffffffu, p2, o);
        const float sx2 = p2;

        float bd = CUDART_INF_F; bi = 0x7fffffff;
        const int limit = (cnt <= CAP) ? cnt : NEMB;
        for (int c = 0; c < limit; c++) {
            int j = (cnt <= CAP) ? g_cand[(size_t)row * CAP + c] : c;
            const float4* e4 = (const float4*)(g_embedT + (size_t)j * DIM);
            float4 e0 = e4[l * 2], e1 = e4[l * 2 + 1];
            float p = 0.0f;
            p = fmaf(xr[0], e0.x, p); p = fmaf(xr[1], e0.y, p);
            p = fmaf(xr[2], e0.z, p); p = fmaf(xr[3], e0.w, p);
            p = fmaf(xr[4], e1.x, p); p = fmaf(xr[5], e1.y, p);
            p = fmaf(xr[6], e1.z, p); p = fmaf(xr[7], e1.w, p);
            #pragma unroll
            for (int o = 16; o > 0; o >>= 1) p += __shfl_xor_sync(0xffffffffu, p, o);
            float se2 = se2_combine(__ldg(&g_sumE2p[j]));
            float d = __fadd_rn(__fsub_rn(sx2, __fmul_rn(2.0f, p)), se2);
            if (d < bd || (d == bd && j < bi)) { bd = d; bi = j; }
        }
    }

    if (l == 0) {
        indOutF[row] = (float)bi;
        atomicAdd(&g_counts[bi], 1);
    }

    // ---- gather + straight-through + diff partial ----
    const float4* erow = (const float4*)(g_embedT + (size_t)bi * DIM);
    float4* qrow = (float4*)(outQ + (size_t)row * DIM);
    float4 e0 = __ldg(&erow[l * 2]);
    float4 e1 = __ldg(&erow[l * 2 + 1]);

    float dx[8];
    dx[0] = __fsub_rn(e0.x, xr[0]); dx[1] = __fsub_rn(e0.y, xr[1]);
    dx[2] = __fsub_rn(e0.z, xr[2]); dx[3] = __fsub_rn(e0.w, xr[3]);
    dx[4] = __fsub_rn(e1.x, xr[4]); dx[5] = __fsub_rn(e1.y, xr[5]);
    dx[6] = __fsub_rn(e1.z, xr[6]); dx[7] = __fsub_rn(e1.w, xr[7]);

    float4 q0, q1;
    q0.x = __fadd_rn(xr[0], dx[0]); q0.y = __fadd_rn(xr[1], dx[1]);
    q0.z = __fadd_rn(xr[2], dx[2]); q0.w = __fadd_rn(xr[3], dx[3]);
    q1.x = __fadd_rn(xr[4], dx[4]); q1.y = __fadd_rn(xr[5], dx[5]);
    q1.z = __fadd_rn(xr[6], dx[6]); q1.w = __fadd_rn(xr[7], dx[7]);
    qrow[l * 2]     = q0;
    qrow[l * 2 + 1] = q1;

    double s = 0.0;
    #pragma unroll
    for (int u = 0; u < 8; u++)
        s += (double)__fmul_rn(dx[u], dx[u]);
    #pragma unroll
    for (int o = 16; o > 0; o >>= 1) s += __shfl_xor_sync(0xffffffffu, s, o);
    if (l == 0) wsum[w] = s;
    __syncthreads();
    if (threadIdx.x == 0) {
        double acc = 0.0;
        #pragma unroll
        for (int i = 0; i < 8; i++) acc += wsum[i];
        g_partials[blockIdx.x] = acc;
        __threadfence();
        unsigned int old = atomicAdd(&g_done, 1u);
        sLast = (old == NPART - 1u) ? 1 : 0;
    }
    __syncthreads();

    // ---- LAST block: deterministic finalize (diff + perplexity) ----
    if (sLast) {
        const int tid = threadIdx.x;
        double acc = 0.0;
        for (int i = tid; i < NPART; i += 256) acc += g_partials[i];
        sred[tid] = acc;
        __syncthreads();
        for (int o = 128; o > 0; o >>= 1) {
            if (tid < o) sred[tid] += sred[tid + o];
            __syncthreads();
        }
        if (tid == 0) *outDiff = (float)(sred[0] / (double)QELEMS);
        __syncthreads();

        double ps = 0.0;
        for (int j = tid; j < NEMB; j += 256) {
            float p  = (float)g_counts[j] * (1.0f / 65536.0f);
            float cl = fmaxf(p, 1e-7f);
            ps += (double)__fmul_rn(p, logf(cl));
        }
        sred[tid] = ps;
        __syncthreads();
        for (int o = 128; o > 0; o >>= 1) {
            if (tid < o) sred[tid] += sred[tid + o];
            __syncthreads();
        }
        if (tid == 0) *outPerp = expf((float)(-sred[0]));
    }
}

// ============================================================
// Output layout (float32): [quantize_st | diff | embed_ind | perplexity]
// ============================================================
extern "C" void kernel_launch(void* const* d_in, const int* in_sizes, int n_in,
                              void* d_out, int out_size) {
    const float* input = (const float*)d_in[0];
    const float* embed = (const float*)d_in[1];
    float* out     = (float*)d_out;
    float* outQ    = out;
    float* outDiff = out + QELEMS;
    float* outInd  = out + QELEMS + 1;
    float* outPerp = out + QELEMS + 1 + NROWS;

    cudaFuncSetAttribute(dist_kernel,
                         cudaFuncAttributeMaxDynamicSharedMemorySize, SMEM_DIST);

    prep_kernel<<<256, 256>>>(embed);
    dist_kernel<<<NROWS / M_CTA, 256, SMEM_DIST>>>(input);
    recheck_gather_kernel<<<NPART, 256>>>(input, outQ, outInd, outDiff, outPerp);
}